// round 2
// baseline (speedup 1.0000x reference)
#include <cuda_runtime.h>
#include <cstdint>

#define NBLK 148
#define NTHR 256

// ---------------- static device scratch ----------------
__device__ float g_P[4849664];          // k-split partial regions (disjoint per stage)
__device__ float g_odec[64 * 1152];     // [attn | out_att | sv]
__device__ float g_res1[64 * 512];
__device__ float g_res2[64 * 512];
__device__ float g_part[64 * 16 * 512]; // attention weighted-sum partials (8 chunks x 2 t-halves)
__device__ float g_wpart[64 * 8];       // attention weight-sum partials
__device__ unsigned g_bar_ctr;          // grid barrier counter (memset to 0 each launch)

// partial-region offsets (floats)
#define OFF_P1 0        // pre1:  ns=3,  ldp=512   (3*64*512)
#define OFF_P2 98304    // pre2:  ns=8,  ldp=256   (8*64*256)
#define OFF_A  229376   // gruA:  ns=12, ldp=1536  (12*64*1536)
#define OFF_W  1409024  // wdec:  ns=16, ldp=512   (16*64*512)
#define OFF_G  1933312  // wsc+g1:ns=9,  ldp=2048  (9*64*2048)
#define OFF_2  3112960  // g2:    ns=16, ldp=1536  (16*64*1536)
#define OFF_O  4685824  // wout:  ns=16, ldp=160   (16*64*160)

__device__ __forceinline__ float tanh_fast(float x) {
    float y; asm("tanh.approx.f32 %0, %1;" : "=f"(y) : "f"(x)); return y;
}
__device__ __forceinline__ float gru_out(float gr, float gz, float gn,
                                         float br, float bz, float bn) {
    float r  = 1.f / (1.f + __expf(-(gr + br)));
    float z  = 1.f / (1.f + __expf(-(gz + bz)));
    float nn = tanhf(gn + r * bn);
    return (1.f - z) * nn;
}

// grid barrier: monotonic counter, CG grid.sync pattern
__device__ __forceinline__ void gbar(unsigned target) {
    __syncthreads();
    if (threadIdx.x == 0) {
        __threadfence();
        atomicAdd(&g_bar_ctr, 1u);
        unsigned v;
        do {
            asm volatile("ld.acquire.gpu.global.u32 %0, [%1];" : "=r"(v) : "l"(&g_bar_ctr));
        } while (v < target);
    }
    __syncthreads();
}

// ---------------- X-element functors (fold previous stage's reduce into loads) ----------------
struct XDirect {
    const float* X; int ldx;
    __device__ __forceinline__ float operator()(int n, int k) const {
        return X[(size_t)n * ldx + k];
    }
};
struct XPre1Red {   // t1 = relu(pb1 + sum of 3 pre1 partials)
    const float* P1; const float* pb1;
    __device__ __forceinline__ float operator()(int n, int k) const {
        float s = pb1[k];
#pragma unroll
        for (int sp = 0; sp < 3; sp++) s += P1[sp * 32768 + n * 512 + k];
        return fmaxf(s, 0.f);
    }
};
struct XPre2Red {   // gruA input: [relu(pre2) (256) | sv (128)]
    const float* P2; const float* pb2; const float* sv;
    __device__ __forceinline__ float operator()(int n, int k) const {
        if (k < 256) {
            float s = pb2[k];
#pragma unroll
            for (int sp = 0; sp < 8; sp++) s += P2[sp * 16384 + n * 256 + k];
            return fmaxf(s, 0.f);
        }
        return sv[n * 128 + (k - 256)];
    }
};

// ---------------- k-split GEMM stage: P[s][n][j] += X[n][k-chunk] . W[j][k-chunk] ----------------
// block tile 128j x 64n, 256 threads, thread tile 4j x 8n.
// xs layout [k][n] stride 68 (f4-aligned), ws layout [k][j] stride 132 (f4-aligned).
template <class XF>
__device__ __forceinline__ void gemm_stage(
    const XF& xf,
    const float* __restrict__ W1, int m1, const float* __restrict__ W2, int ldw,
    int kjump_at, int kjump_ofs,
    int M, int K, int jt_n, int kc, int ks_n,
    float* __restrict__ P, int ldp,
    float* __restrict__ xs, float* __restrict__ ws)
{
    const int tid = threadIdx.x;
    const int items = jt_n * ks_n;
    for (int it = blockIdx.x; it < items; it += NBLK) {
        const int ksp = it / jt_n;
        const int jt  = it - ksp * jt_n;
        const int j0  = jt << 7;
        const int k0  = ksp * kc;
        const int kn  = min(kc, K - k0);
        // X gather: float4 across n (coalesced gmem by k within warp)
        for (int idx = tid; idx < kn * 16; idx += NTHR) {
            int k = idx % kn, n4 = idx / kn;
            float4 v;
            v.x = xf(n4 * 4 + 0, k0 + k);
            v.y = xf(n4 * 4 + 1, k0 + k);
            v.z = xf(n4 * 4 + 2, k0 + k);
            v.w = xf(n4 * 4 + 3, k0 + k);
            *reinterpret_cast<float4*>(xs + k * 68 + n4 * 4) = v;
        }
        // W gather: float4 across j (coalesced gmem by k within warp)
        const int wofs = k0 + (k0 >= kjump_at ? kjump_ofs : 0);
        for (int idx = tid; idx < kn * 32; idx += NTHR) {
            int k = idx % kn, j4 = idx / kn;
            float4 v; float* vp = reinterpret_cast<float*>(&v);
#pragma unroll
            for (int q = 0; q < 4; q++) {
                int jr = j0 + j4 * 4 + q;
                float val = 0.f;
                if (jr < M) {
                    const float* Wr = (jr < m1) ? (W1 + (size_t)jr * ldw)
                                                : (W2 + (size_t)(jr - m1) * ldw);
                    val = Wr[wofs + k];
                }
                vp[q] = val;
            }
            *reinterpret_cast<float4*>(ws + k * 132 + j4 * 4) = v;
        }
        __syncthreads();

        const int tj = tid & 31, tn = tid >> 5;
        float acc[4][8];
#pragma unroll
        for (int a = 0; a < 4; a++)
#pragma unroll
            for (int b = 0; b < 8; b++) acc[a][b] = 0.f;

#pragma unroll 4
        for (int k = 0; k < kn; k++) {
            float4 wv = *reinterpret_cast<const float4*>(ws + k * 132 + tj * 4);
            float4 xa = *reinterpret_cast<const float4*>(xs + k * 68 + tn * 8);
            float4 xb = *reinterpret_cast<const float4*>(xs + k * 68 + tn * 8 + 4);
            float xv[8] = {xa.x, xa.y, xa.z, xa.w, xb.x, xb.y, xb.z, xb.w};
            float wr[4] = {wv.x, wv.y, wv.z, wv.w};
#pragma unroll
            for (int jj = 0; jj < 4; jj++)
#pragma unroll
                for (int i = 0; i < 8; i++) acc[jj][i] += wr[jj] * xv[i];
        }

        if (j0 + tj * 4 < M) {
            float* base = P + (size_t)ksp * (64 * ldp) + j0 + tj * 4;
#pragma unroll
            for (int i = 0; i < 8; i++) {
                int n = tn * 8 + i;
                *reinterpret_cast<float4*>(base + (size_t)n * ldp) =
                    make_float4(acc[0][i], acc[1][i], acc[2][i], acc[3][i]);
            }
        }
        __syncthreads();
    }
}

// ---------------- reduce phases ----------------
__device__ void reduce_gru3(const float* __restrict__ P, int ldp, int ns,
                            const float* __restrict__ bih, const float* __restrict__ bhh,
                            const float* __restrict__ resin,
                            float* __restrict__ out, int ldo, int oofs)
{
    for (int idx = blockIdx.x * NTHR + threadIdx.x; idx < 64 * 512; idx += NBLK * NTHR) {
        int n = idx >> 9, j = idx & 511;
        float gr = bih[j], gz = bih[512 + j], gn = bih[1024 + j];
        const float* pb = P + (size_t)n * ldp;
        for (int s = 0; s < ns; s++) {
            const float* pp = pb + (size_t)s * 64 * ldp;
            gr += pp[j]; gz += pp[512 + j]; gn += pp[1024 + j];
        }
        float v = gru_out(gr, gz, gn, bhh[j], bhh[512 + j], bhh[1024 + j]);
        if (resin) v += resin[idx];
        out[(size_t)n * ldo + oofs + j] = v;
    }
}

__device__ void reduce_scgru(const float* __restrict__ P, int ns,
                             const float* __restrict__ bsc,
                             const float* __restrict__ bih, const float* __restrict__ bhh,
                             float* __restrict__ out)
{
    for (int idx = blockIdx.x * NTHR + threadIdx.x; idx < 64 * 512; idx += NBLK * NTHR) {
        int n = idx >> 9, j = idx & 511;
        float sc = bsc[j], gr = bih[j], gz = bih[512 + j], gn = bih[1024 + j];
        for (int s = 0; s < ns; s++) {
            const float* pp = P + (size_t)s * 64 * 2048 + (size_t)n * 2048;
            sc += pp[j]; gr += pp[512 + j]; gz += pp[1024 + j]; gn += pp[1536 + j];
        }
        out[idx] = sc + gru_out(gr, gz, gn, bhh[j], bhh[512 + j], bhh[1024 + j]);
    }
}

// ---------------- fused attention phase ----------------
// per item (n, 128-t chunk): build attW from wdec partials, score+exp, weighted sums.
__device__ void attention_phase(const float* __restrict__ encW, const float* __restrict__ enc,
                                const float* __restrict__ wattn, const float* __restrict__ battn,
                                const float* __restrict__ bdec, const float* __restrict__ PW,
                                const int* __restrict__ len, float* __restrict__ sm)
{
    float* aw = sm; float* wv = sm + 512; float* we = sm + 1024; float* wred = sm + 1152;
    const int tid = threadIdx.x, lane = tid & 31, warp = tid >> 5;
    for (int item = blockIdx.x; item < 512; item += NBLK) {
        const int n = item >> 3, ch = item & 7, t0 = ch << 7;
        const int L = len[n];
        const int tc = min(128, L - t0);
        if (tc > 0) {
            for (int c = tid; c < 512; c += NTHR) {
                float s = bdec[c];
#pragma unroll
                for (int sp = 0; sp < 16; sp++) s += PW[sp * 32768 + n * 512 + c];
                aw[c] = s; wv[c] = wattn[c];
            }
            __syncthreads();
            float wsumw = 0.f;
            float bat = battn[0];
            for (int tt = warp; tt < tc; tt += 8) {
                const float* row = encW + ((size_t)(n * 1024 + t0 + tt)) * 512;
                float s = 0.f;
#pragma unroll
                for (int q = 0; q < 4; q++) {
                    int c = q * 128 + lane * 4;
                    float4 v = *reinterpret_cast<const float4*>(row + c);
                    float4 a = *reinterpret_cast<const float4*>(aw + c);
                    float4 w = *reinterpret_cast<const float4*>(wv + c);
                    s += tanh_fast(v.x + a.x) * w.x + tanh_fast(v.y + a.y) * w.y
                       + tanh_fast(v.z + a.z) * w.z + tanh_fast(v.w + a.w) * w.w;
                }
#pragma unroll
                for (int o = 16; o > 0; o >>= 1) s += __shfl_xor_sync(0xffffffffu, s, o);
                if (lane == 0) { float e = __expf(s + bat); we[tt] = e; wsumw += e; }
            }
            if (lane == 0) wred[warp] = wsumw;
            __syncthreads();
            if (tid == 0) {
                float s = 0.f;
#pragma unroll
                for (int w = 0; w < 8; w++) s += wred[w];
                g_wpart[n * 8 + ch] = s;
            }
            // weighted sum: 128 col-groups (float4) x 2 t-halves
            const int half = tid >> 7;
            const int cg = (tid & 127) << 2;
            const int tb = half * 64;
            const int te = min(tc, tb + 64);
            const float* eb = enc + ((size_t)(n * 1024 + t0)) * 512 + cg;
            float ax = 0.f, ay = 0.f, az = 0.f, a2 = 0.f;
            int t = tb;
            for (; t + 8 <= te; t += 8) {
#pragma unroll
                for (int u = 0; u < 8; u++) {
                    float w = we[t + u];
                    float4 v = *reinterpret_cast<const float4*>(eb + (size_t)(t + u) * 512);
                    ax += w * v.x; ay += w * v.y; az += w * v.z; a2 += w * v.w;
                }
            }
            for (; t < te; t++) {
                float w = we[t];
                float4 v = *reinterpret_cast<const float4*>(eb + (size_t)t * 512);
                ax += w * v.x; ay += w * v.y; az += w * v.z; a2 += w * v.w;
            }
            *reinterpret_cast<float4*>(&g_part[((size_t)(n * 16 + ch * 2 + half)) * 512 + cg]) =
                make_float4(ax, ay, az, a2);
            __syncthreads();
        } else {
            for (int c = tid; c < 512; c += NTHR) {
                g_part[(size_t)(n * 16 + ch * 2 + 0) * 512 + c] = 0.f;
                g_part[(size_t)(n * 16 + ch * 2 + 1) * 512 + c] = 0.f;
            }
            if (tid == 0) g_wpart[n * 8 + ch] = 0.f;
        }
    }
}

// ---------------- the mega kernel ----------------
struct MArgs {
    const float *enc, *encW, *dec, *sv;
    const int* len;
    const float *pw1, *pb1, *pw2, *pb2, *wdec_, *bdec;
    const float *ga_ih, *ga_bih, *ga_bhh, *wattn, *battn;
    const float *wsc, *bsc, *g1_ih, *g1_bih, *g1_bhh;
    const float *g2_ih, *g2_bih, *g2_bhh, *wout_, *bout;
    float* out;
};

__global__ __launch_bounds__(NTHR) void mega(MArgs a)
{
    extern __shared__ float sm[];
    float* xs = sm;           // 128*68 = 8704 floats
    float* ws = sm + 8704;    // 128*132 = 16896 floats  (total 102400 B)
    const int tid = threadIdx.x;
    const int BIGJ = 1 << 30;
    unsigned bt = 0;

    // S1: pre1 partials (M=512, K=80, jt=4, kc=32, ks=3) + sv -> odec[1024:1152]
    gemm_stage(XDirect{a.dec, 80}, a.pw1, BIGJ, a.pw1, 80, BIGJ, 0,
               512, 80, 4, 32, 3, g_P + OFF_P1, 512, xs, ws);
    for (int idx = blockIdx.x * NTHR + tid; idx < 64 * 128; idx += NBLK * NTHR) {
        int n = idx >> 7, c = idx & 127;
        g_odec[n * 1152 + 1024 + c] = a.sv[n * 128 + c];
    }
    bt += NBLK; gbar(bt);

    // S2: pre2 partials (M=256, K=512, jt=2, kc=64, ks=8); X = relu(pre1-reduce)
    gemm_stage(XPre1Red{g_P + OFF_P1, a.pb1}, a.pw2, BIGJ, a.pw2, 512, BIGJ, 0,
               256, 512, 2, 64, 8, g_P + OFF_P2, 256, xs, ws);
    bt += NBLK; gbar(bt);

    // S4: gruA input GEMM (M=1536, K=384=[pre 256|sv 128], jt=12, kc=32, ks=12)
    //     W cols: k<256 -> ga_ih col k ; k>=256 -> col k+512 (sv block at 768:896)
    gemm_stage(XPre2Red{g_P + OFF_P2, a.pb2, a.sv}, a.ga_ih, BIGJ, a.ga_ih, 896, 256, 512,
               1536, 384, 12, 32, 12, g_P + OFF_A, 1536, xs, ws);
    bt += NBLK; gbar(bt);

    // S5: gruA reduce -> out_att -> odec[512:1024]
    reduce_gru3(g_P + OFF_A, 1536, 12, a.ga_bih, a.ga_bhh, nullptr, g_odec, 1152, 512);
    bt += NBLK; gbar(bt);

    // S6: wdec partials (M=512, K=512, jt=4, kc=32, ks=16); X = out_att
    gemm_stage(XDirect{g_odec + 512, 1152}, a.wdec_, BIGJ, a.wdec_, 512, BIGJ, 0,
               512, 512, 4, 32, 16, g_P + OFF_W, 512, xs, ws);
    bt += NBLK; gbar(bt);

    // S8: fused attention (score + exp + weighted sums), attW built from wdec partials
    attention_phase(a.encW, a.enc, a.wattn, a.battn, a.bdec, g_P + OFF_W, a.len, sm);
    bt += NBLK; gbar(bt);

    // S9: attention reduce -> odec[0:512] and d_out attn section
    for (int idx = blockIdx.x * NTHR + tid; idx < 64 * 512; idx += NBLK * NTHR) {
        int n = idx >> 9, c = idx & 511;
        float s = 0.f;
#pragma unroll
        for (int sub = 0; sub < 16; sub++) s += g_part[(size_t)(n * 16 + sub) * 512 + c];
        float wsum = 0.f;
#pragma unroll
        for (int ch = 0; ch < 8; ch++) wsum += g_wpart[n * 8 + ch];
        float v = s / fmaxf(wsum, 1e-12f);
        g_odec[n * 1152 + c] = v;
        a.out[10240 + (size_t)n * 512 + c] = v;
    }
    bt += NBLK; gbar(bt);

    // S10: fused wsc|g1 GEMM (M=2048, K=1152, jt=16, kc=128, ks=9); X = odec
    gemm_stage(XDirect{g_odec, 1152}, a.wsc, 512, a.g1_ih, 1152, BIGJ, 0,
               2048, 1152, 16, 128, 9, g_P + OFF_G, 2048, xs, ws);
    bt += NBLK; gbar(bt);

    // S11: residual = sc + gru1 -> res1
    reduce_scgru(g_P + OFF_G, 9, a.bsc, a.g1_bih, a.g1_bhh, g_res1);
    bt += NBLK; gbar(bt);

    // S12: g2 GEMM (M=1536, K=512, jt=12, kc=32, ks=16); X = res1
    gemm_stage(XDirect{g_res1, 512}, a.g2_ih, BIGJ, a.g2_ih, 512, BIGJ, 0,
               1536, 512, 12, 32, 16, g_P + OFF_2, 1536, xs, ws);
    bt += NBLK; gbar(bt);

    // S13: res2 = res1 + gru2
    reduce_gru3(g_P + OFF_2, 1536, 16, a.g2_bih, a.g2_bhh, g_res1, g_res2, 512, 0);
    bt += NBLK; gbar(bt);

    // S14: wout GEMM (M=160, K=512, jt=2, kc=32, ks=16); X = res2
    gemm_stage(XDirect{g_res2, 512}, a.wout_, BIGJ, a.wout_, 512, BIGJ, 0,
               160, 512, 2, 32, 16, g_P + OFF_O, 160, xs, ws);
    bt += NBLK; gbar(bt);

    // S15: wout reduce -> d_out[0:10240]
    for (int idx = blockIdx.x * NTHR + tid; idx < 64 * 160; idx += NBLK * NTHR) {
        int n = idx / 160, j = idx - n * 160;
        float s = a.bout[j];
#pragma unroll
        for (int sp = 0; sp < 16; sp++) s += g_P[OFF_O + sp * 10240 + n * 160 + j];
        a.out[idx] = s;
    }
}

// ---------------- host orchestration ----------------
extern "C" void kernel_launch(void* const* d_in, const int* in_sizes, int n_in,
                              void* d_out, int out_size)
{
    (void)n_in; (void)out_size;
    bool dictord = (in_sizes[4] == 64);
    int b = dictord ? 5 : 4;

    MArgs a;
    a.enc   = (const float*)d_in[0];
    a.encW  = (const float*)d_in[1];
    a.dec   = (const float*)d_in[2];
    a.sv    = (const float*)d_in[3];
    a.len   = (const int*)(dictord ? d_in[4] : d_in[28]);
    a.pw1   = (const float*)d_in[b + 0];
    a.pb1   = (const float*)d_in[b + 1];
    a.pw2   = (const float*)d_in[b + 2];
    a.pb2   = (const float*)d_in[b + 3];
    a.wdec_ = (const float*)d_in[b + 4];
    a.bdec  = (const float*)d_in[b + 5];
    a.ga_ih = (const float*)d_in[b + 6];
    a.ga_bih= (const float*)d_in[b + 8];
    a.ga_bhh= (const float*)d_in[b + 9];
    a.wattn = (const float*)d_in[b + 10];
    a.battn = (const float*)d_in[b + 11];
    a.wsc   = (const float*)d_in[b + 12];
    a.bsc   = (const float*)d_in[b + 13];
    a.g1_ih = (const float*)d_in[b + 14];
    a.g1_bih= (const float*)d_in[b + 16];
    a.g1_bhh= (const float*)d_in[b + 17];
    a.g2_ih = (const float*)d_in[b + 18];
    a.g2_bih= (const float*)d_in[b + 20];
    a.g2_bhh= (const float*)d_in[b + 21];
    a.wout_ = (const float*)d_in[b + 22];
    a.bout  = (const float*)d_in[b + 23];
    a.out   = (float*)d_out;

    static bool attr_set = false;
    if (!attr_set) {
        cudaFuncSetAttribute(mega, cudaFuncAttributeMaxDynamicSharedMemorySize, 102400);
        attr_set = true;
    }

    void* ctr;
    cudaGetSymbolAddress(&ctr, g_bar_ctr);
    cudaMemsetAsync(ctr, 0, sizeof(unsigned));

    mega<<<NBLK, NTHR, 102400>>>(a);
}

// round 4
// speedup vs baseline: 1.4025x; 1.4025x over previous
#include <cuda_runtime.h>
#include <cstdint>

#define NBLK 148
#define NTHR 512

// ---------------- static device scratch ----------------
__device__ __align__(16) float g_P[5767168];
__device__ __align__(16) float g_oatt[64 * 512];
__device__ __align__(16) float g_res1[64 * 512];
__device__ __align__(16) float g_part[64 * 8 * 512];
__device__ __align__(16) float g_wpart[512];
__device__ unsigned g_ctrs[2];   // [0]=barrier, [1]=attention steal; memset per launch

// partial-region offsets (floats)
#define OFF_P1 0        // pre1:  ns=3,  ldp=512
#define OFF_P2 98304    // pre2:  ns=8,  ldp=256
#define OFF_A  229376   // gruA:  ns=12, ldp=1536
#define OFF_W  1409024  // wdec:  ns=8,  ldp=512
#define OFF_G  1671168  // wsc|g1:ns=18, ldp=2048
#define OFF_2  4030464  // g2:    ns=16, ldp=1536
#define OFF_O  5603328  // wout:  ns=16, ldp=160

__device__ __forceinline__ float tanh_fast(float x) {
    float y; asm("tanh.approx.f32 %0, %1;" : "=f"(y) : "f"(x)); return y;
}
__device__ __forceinline__ float gru_out(float gr, float gz, float gn,
                                         float br, float bz, float bn) {
    float r  = 1.f / (1.f + __expf(-(gr + br)));
    float z  = 1.f / (1.f + __expf(-(gz + bz)));
    float nn = tanhf(gn + r * bn);
    return (1.f - z) * nn;
}
__device__ __forceinline__ void add4(float4& a, const float4 b) {
    a.x += b.x; a.y += b.y; a.z += b.z; a.w += b.w;
}
__device__ __forceinline__ void bar_half(int half) {
    asm volatile("bar.sync %0, 256;" :: "r"(half + 1) : "memory");
}

// grid barrier (all 148 CTAs guaranteed resident: 1 CTA/SM by construction)
__device__ __forceinline__ void gbar(unsigned target) {
    __syncthreads();
    if (threadIdx.x == 0) {
        __threadfence();
        asm volatile("red.release.gpu.global.add.u32 [%0], %1;"
                     :: "l"(&g_ctrs[0]), "r"(1u) : "memory");
        unsigned v;
        do {
            asm volatile("ld.acquire.gpu.global.u32 %0, [%1];"
                         : "=r"(v) : "l"(&g_ctrs[0]) : "memory");
        } while (v < target);
    }
    __syncthreads();
}

// ---------------- X functors ----------------
struct XDirect {
    const float* X; int ldx;
    __device__ __forceinline__ float4 load4(int n, int k) const {
        return *reinterpret_cast<const float4*>(X + (size_t)n * ldx + k);
    }
    __device__ __forceinline__ float load1(int n, int k) const {
        return X[(size_t)n * ldx + k];
    }
};
struct XPre1Red {   // t1 = relu(pb1 + sum of 3 pre1 partials)
    const float* P1; const float* pb1;
    __device__ __forceinline__ float4 load4(int n, int k) const {
        float4 s = *reinterpret_cast<const float4*>(pb1 + k);
#pragma unroll
        for (int sp = 0; sp < 3; sp++)
            add4(s, *reinterpret_cast<const float4*>(P1 + sp * 32768 + n * 512 + k));
        s.x = fmaxf(s.x, 0.f); s.y = fmaxf(s.y, 0.f);
        s.z = fmaxf(s.z, 0.f); s.w = fmaxf(s.w, 0.f);
        return s;
    }
    __device__ __forceinline__ float load1(int n, int k) const {
        float s = pb1[k];
        for (int sp = 0; sp < 3; sp++) s += P1[sp * 32768 + n * 512 + k];
        return fmaxf(s, 0.f);
    }
};
struct XPre2Red {   // gruA input: [relu(pre2-reduce) (256) | sv (128)]
    const float* P2; const float* pb2; const float* sv;
    __device__ __forceinline__ float4 load4(int n, int k) const {
        if (k < 256) {
            float4 s = *reinterpret_cast<const float4*>(pb2 + k);
#pragma unroll
            for (int sp = 0; sp < 8; sp++)
                add4(s, *reinterpret_cast<const float4*>(P2 + sp * 16384 + n * 256 + k));
            s.x = fmaxf(s.x, 0.f); s.y = fmaxf(s.y, 0.f);
            s.z = fmaxf(s.z, 0.f); s.w = fmaxf(s.w, 0.f);
            return s;
        }
        return *reinterpret_cast<const float4*>(sv + n * 128 + (k - 256));
    }
    __device__ __forceinline__ float load1(int n, int k) const {
        if (k < 256) {
            float s = pb2[k];
            for (int sp = 0; sp < 8; sp++) s += P2[sp * 16384 + n * 256 + k];
            return fmaxf(s, 0.f);
        }
        return sv[n * 128 + (k - 256)];
    }
};
struct XGruARed {   // out_att element from gruA partials (12 splits, ldp=1536)
    const float* P; const float* bih; const float* bhh;
    __device__ __forceinline__ float4 load4(int n, int k) const {
        const float* b = P + (size_t)n * 1536 + k;
        float4 r = *reinterpret_cast<const float4*>(bih + k);
        float4 z = *reinterpret_cast<const float4*>(bih + 512 + k);
        float4 m = *reinterpret_cast<const float4*>(bih + 1024 + k);
#pragma unroll
        for (int sp = 0; sp < 12; sp++) {
            const float* q = b + (size_t)sp * 98304;
            add4(r, *reinterpret_cast<const float4*>(q));
            add4(z, *reinterpret_cast<const float4*>(q + 512));
            add4(m, *reinterpret_cast<const float4*>(q + 1024));
        }
        float4 br = *reinterpret_cast<const float4*>(bhh + k);
        float4 bz = *reinterpret_cast<const float4*>(bhh + 512 + k);
        float4 bn = *reinterpret_cast<const float4*>(bhh + 1024 + k);
        float4 o;
        o.x = gru_out(r.x, z.x, m.x, br.x, bz.x, bn.x);
        o.y = gru_out(r.y, z.y, m.y, br.y, bz.y, bn.y);
        o.z = gru_out(r.z, z.z, m.z, br.z, bz.z, bn.z);
        o.w = gru_out(r.w, z.w, m.w, br.w, bz.w, bn.w);
        return o;
    }
    __device__ __forceinline__ float load1(int n, int k) const {
        float gr = bih[k], gz = bih[512 + k], gn = bih[1024 + k];
        for (int sp = 0; sp < 12; sp++) {
            const float* q = P + (size_t)sp * 98304 + (size_t)n * 1536 + k;
            gr += q[0]; gz += q[512]; gn += q[1024];
        }
        return gru_out(gr, gz, gn, bhh[k], bhh[512 + k], bhh[1024 + k]);
    }
};
struct XOdecRed {   // out_dec: [attn-normalize | out_att | sv]
    const float* part; const float* wpart; const float* oatt; const float* sv;
    __device__ __forceinline__ float4 load4(int n, int k) const {
        if (k < 512) {
            float4 s = make_float4(0.f, 0.f, 0.f, 0.f);
            float w = 0.f;
#pragma unroll
            for (int sp = 0; sp < 8; sp++) {
                add4(s, *reinterpret_cast<const float4*>(part + (size_t)(n * 8 + sp) * 512 + k));
                w += wpart[n * 8 + sp];
            }
            float inv = 1.f / fmaxf(w, 1e-12f);
            s.x *= inv; s.y *= inv; s.z *= inv; s.w *= inv;
            return s;
        }
        if (k < 1024) return *reinterpret_cast<const float4*>(oatt + n * 512 + (k - 512));
        return *reinterpret_cast<const float4*>(sv + n * 128 + (k - 1024));
    }
    __device__ __forceinline__ float load1(int n, int k) const {
        if (k < 512) {
            float s = 0.f, w = 0.f;
            for (int sp = 0; sp < 8; sp++) {
                s += part[(size_t)(n * 8 + sp) * 512 + k];
                w += wpart[n * 8 + sp];
            }
            return s / fmaxf(w, 1e-12f);
        }
        if (k < 1024) return oatt[n * 512 + (k - 512)];
        return sv[n * 128 + (k - 1024)];
    }
};
struct XGru2Red {   // res2 element = res1 + gru2 from partials (16 splits, ldp=1536)
    const float* P; const float* bih; const float* bhh; const float* res1;
    __device__ __forceinline__ float4 load4(int n, int k) const {
        const float* b = P + (size_t)n * 1536 + k;
        float4 r = *reinterpret_cast<const float4*>(bih + k);
        float4 z = *reinterpret_cast<const float4*>(bih + 512 + k);
        float4 m = *reinterpret_cast<const float4*>(bih + 1024 + k);
#pragma unroll
        for (int sp = 0; sp < 16; sp++) {
            const float* q = b + (size_t)sp * 98304;
            add4(r, *reinterpret_cast<const float4*>(q));
            add4(z, *reinterpret_cast<const float4*>(q + 512));
            add4(m, *reinterpret_cast<const float4*>(q + 1024));
        }
        float4 br = *reinterpret_cast<const float4*>(bhh + k);
        float4 bz = *reinterpret_cast<const float4*>(bhh + 512 + k);
        float4 bn = *reinterpret_cast<const float4*>(bhh + 1024 + k);
        float4 rv = *reinterpret_cast<const float4*>(res1 + n * 512 + k);
        float4 o;
        o.x = gru_out(r.x, z.x, m.x, br.x, bz.x, bn.x) + rv.x;
        o.y = gru_out(r.y, z.y, m.y, br.y, bz.y, bn.y) + rv.y;
        o.z = gru_out(r.z, z.z, m.z, br.z, bz.z, bn.z) + rv.z;
        o.w = gru_out(r.w, z.w, m.w, br.w, bz.w, bn.w) + rv.w;
        return o;
    }
    __device__ __forceinline__ float load1(int n, int k) const {
        float gr = bih[k], gz = bih[512 + k], gn = bih[1024 + k];
        for (int sp = 0; sp < 16; sp++) {
            const float* q = P + (size_t)sp * 98304 + (size_t)n * 1536 + k;
            gr += q[0]; gz += q[512]; gn += q[1024];
        }
        return gru_out(gr, gz, gn, bhh[k], bhh[512 + k], bhh[1024 + k]) + res1[n * 512 + k];
    }
};

// ---------------- dual-worker k-split GEMM stage ----------------
// Each 256-thread half is an independent worker: tile 128j x 64n, 4j x 8n/thread.
template <int KC, class XF>
__device__ __forceinline__ void gemm_stage(
    const XF xf,
    const float* __restrict__ W1, int m1, const float* __restrict__ W2, int ldw,
    int kjump_at, int kjump_ofs,
    int M, int K, int jt_n, int ks_n,
    float* __restrict__ P, int ldp, float* __restrict__ smh, int half, int htid)
{
    constexpr int K4 = KC / 4;
    constexpr int SH = (KC == 64) ? 4 : 3;
    float* xs = smh;            // [KC][68]
    float* ws = smh + KC * 68;  // [KC][132]
    const int items = jt_n * ks_n;

    for (int it = blockIdx.x * 2 + half; it < items; it += 2 * NBLK) {
        const int ksp = it / jt_n;
        const int jt  = it - ksp * jt_n;
        const int j0  = jt << 7;
        const int k0  = ksp * KC;
        // X gather: float4 along k -> xs[k][n]
        for (int idx = htid; idx < K4 * 64; idx += 256) {
            int k4 = idx & (K4 - 1), n = idx >> SH;
            int kk = k0 + (k4 << 2);
            float4 v = make_float4(0.f, 0.f, 0.f, 0.f);
            if (kk + 3 < K) v = xf.load4(n, kk);
            else {
                if (kk + 0 < K) v.x = xf.load1(n, kk + 0);
                if (kk + 1 < K) v.y = xf.load1(n, kk + 1);
                if (kk + 2 < K) v.z = xf.load1(n, kk + 2);
                if (kk + 3 < K) v.w = xf.load1(n, kk + 3);
            }
            float* d = xs + (k4 << 2) * 68 + n;
            d[0] = v.x; d[68] = v.y; d[136] = v.z; d[204] = v.w;
        }
        // W gather: float4 along k -> ws[k][j]
        const int wofs = k0 + (k0 >= kjump_at ? kjump_ofs : 0);
        for (int idx = htid; idx < K4 * 128; idx += 256) {
            int k4 = idx & (K4 - 1), j = idx >> SH;
            int jr = j0 + j;
            float4 v = make_float4(0.f, 0.f, 0.f, 0.f);
            if (jr < M) {
                const float* Wr = (jr < m1) ? (W1 + (size_t)jr * ldw)
                                            : (W2 + (size_t)(jr - m1) * ldw);
                int kk = k0 + (k4 << 2);
                if (kk + 3 < K) v = *reinterpret_cast<const float4*>(Wr + wofs + (k4 << 2));
                else {
                    if (kk + 0 < K) v.x = Wr[wofs + (k4 << 2) + 0];
                    if (kk + 1 < K) v.y = Wr[wofs + (k4 << 2) + 1];
                    if (kk + 2 < K) v.z = Wr[wofs + (k4 << 2) + 2];
                    if (kk + 3 < K) v.w = Wr[wofs + (k4 << 2) + 3];
                }
            }
            float* d = ws + (k4 << 2) * 132 + j;
            d[0] = v.x; d[132] = v.y; d[264] = v.z; d[396] = v.w;
        }
        bar_half(half);

        const int tj = htid & 31, tn = htid >> 5;
        float acc[4][8];
#pragma unroll
        for (int a = 0; a < 4; a++)
#pragma unroll
            for (int b = 0; b < 8; b++) acc[a][b] = 0.f;

#pragma unroll 8
        for (int k = 0; k < KC; k++) {
            float4 wv = *reinterpret_cast<const float4*>(ws + k * 132 + tj * 4);
            float4 xa = *reinterpret_cast<const float4*>(xs + k * 68 + tn * 8);
            float4 xb = *reinterpret_cast<const float4*>(xs + k * 68 + tn * 8 + 4);
            float xv[8] = {xa.x, xa.y, xa.z, xa.w, xb.x, xb.y, xb.z, xb.w};
            float wr[4] = {wv.x, wv.y, wv.z, wv.w};
#pragma unroll
            for (int jj = 0; jj < 4; jj++)
#pragma unroll
                for (int i = 0; i < 8; i++) acc[jj][i] += wr[jj] * xv[i];
        }

        if (j0 + tj * 4 < M) {
            float* base = P + (size_t)ksp * (64 * ldp) + j0 + tj * 4;
#pragma unroll
            for (int i = 0; i < 8; i++) {
                int n = tn * 8 + i;
                *reinterpret_cast<float4*>(base + (size_t)n * ldp) =
                    make_float4(acc[0][i], acc[1][i], acc[2][i], acc[3][i]);
            }
        }
        bar_half(half);
    }
}

// ---------------- fused attention phase (per-half work-stealing) ----------------
__device__ void attention_phase(const float* __restrict__ encW, const float* __restrict__ enc,
                                const float* __restrict__ wattn, const float* __restrict__ battn,
                                const float* __restrict__ bdec, const int* __restrict__ len,
                                float* __restrict__ smh, int half, int htid)
{
    float* wv_s = smh;          // 512
    float* aw_s = smh + 512;    // 512
    float* wacc = smh + 1024;   // 8*512
    int*   ip   = (int*)(smh + 5120);
    float* wred = smh + 5124;   // 8
    const float* PW = g_P + OFF_W;
    const int lane = htid & 31, warp = htid >> 5;
    const float bat = battn[0];

    for (int c = htid; c < 512; c += 256) wv_s[c] = wattn[c];

    for (;;) {
        if (htid == 0) *ip = (int)atomicAdd(&g_ctrs[1], 1u);
        bar_half(half);
        const int item = *ip;
        if (item >= 512) break;
        const int n = item >> 3, ch = item & 7, t0 = ch << 7;
        const int tc = min(128, len[n] - t0);

        if (tc > 0) {
            // build attW[n] from wdec partials (+ bdec)
            for (int c4 = htid; c4 < 128; c4 += 256) {
                int c = c4 << 2;
                float4 s = *reinterpret_cast<const float4*>(bdec + c);
#pragma unroll
                for (int sp = 0; sp < 8; sp++)
                    add4(s, *reinterpret_cast<const float4*>(PW + sp * 32768 + n * 512 + c));
                *reinterpret_cast<float4*>(aw_s + c) = s;
            }
            bar_half(half);

            float4 facc[4];
#pragma unroll
            for (int q = 0; q < 4; q++) facc[q] = make_float4(0.f, 0.f, 0.f, 0.f);
            float wsum = 0.f;
            const size_t rb = ((size_t)(n * 1024 + t0)) * 512;

            for (int tb = warp * 2; tb < tc; tb += 16) {
                const bool ok1 = (tb + 1 < tc);
                const float* rW0 = encW + rb + (size_t)tb * 512;
                const float* rE0 = enc  + rb + (size_t)tb * 512;
                float4 a0[4], a1[4], f0[4], f1[4];
#pragma unroll
                for (int q = 0; q < 4; q++) {
                    int c = lane * 4 + q * 128;
                    a0[q] = *reinterpret_cast<const float4*>(rW0 + c);
                    f0[q] = *reinterpret_cast<const float4*>(rE0 + c);
                    if (ok1) {
                        a1[q] = *reinterpret_cast<const float4*>(rW0 + 512 + c);
                        f1[q] = *reinterpret_cast<const float4*>(rE0 + 512 + c);
                    } else {
                        a1[q] = make_float4(0.f, 0.f, 0.f, 0.f);
                        f1[q] = make_float4(0.f, 0.f, 0.f, 0.f);
                    }
                }
                float s0 = 0.f, s1 = 0.f;
#pragma unroll
                for (int q = 0; q < 4; q++) {
                    int c = lane * 4 + q * 128;
                    float4 aw = *reinterpret_cast<const float4*>(aw_s + c);
                    float4 wv = *reinterpret_cast<const float4*>(wv_s + c);
                    s0 += tanh_fast(a0[q].x + aw.x) * wv.x + tanh_fast(a0[q].y + aw.y) * wv.y
                        + tanh_fast(a0[q].z + aw.z) * wv.z + tanh_fast(a0[q].w + aw.w) * wv.w;
                    s1 += tanh_fast(a1[q].x + aw.x) * wv.x + tanh_fast(a1[q].y + aw.y) * wv.y
                        + tanh_fast(a1[q].z + aw.z) * wv.z + tanh_fast(a1[q].w + aw.w) * wv.w;
                }
#pragma unroll
                for (int o = 16; o > 0; o >>= 1) {
                    s0 += __shfl_xor_sync(0xffffffffu, s0, o);
                    s1 += __shfl_xor_sync(0xffffffffu, s1, o);
                }
                float w0 = __expf(s0 + bat);
                float w1 = ok1 ? __expf(s1 + bat) : 0.f;
                wsum += w0 + w1;
#pragma unroll
                for (int q = 0; q < 4; q++) {
                    facc[q].x += w0 * f0[q].x + w1 * f1[q].x;
                    facc[q].y += w0 * f0[q].y + w1 * f1[q].y;
                    facc[q].z += w0 * f0[q].z + w1 * f1[q].z;
                    facc[q].w += w0 * f0[q].w + w1 * f1[q].w;
                }
            }
#pragma unroll
            for (int q = 0; q < 4; q++)
                *reinterpret_cast<float4*>(wacc + warp * 512 + lane * 4 + q * 128) = facc[q];
            if (lane == 0) wred[warp] = wsum;
            bar_half(half);
            for (int c = htid; c < 512; c += 256) {
                float s = 0.f;
#pragma unroll
                for (int w = 0; w < 8; w++) s += wacc[w * 512 + c];
                g_part[(size_t)item * 512 + c] = s;
            }
            if (htid == 0) {
                float s = 0.f;
#pragma unroll
                for (int w = 0; w < 8; w++) s += wred[w];
                g_wpart[item] = s;
            }
            bar_half(half);
        } else {
            for (int c = htid; c < 512; c += 256) g_part[(size_t)item * 512 + c] = 0.f;
            if (htid == 0) g_wpart[item] = 0.f;
        }
    }
}

// ---------------- the mega kernel ----------------
struct MArgs {
    const float *enc, *encW, *dec, *sv;
    const int* len;
    const float *pw1, *pb1, *pw2, *pb2, *wdec_, *bdec;
    const float *ga_ih, *ga_bih, *ga_bhh, *wattn, *battn;
    const float *wsc, *bsc, *g1_ih, *g1_bih, *g1_bhh;
    const float *g2_ih, *g2_bih, *g2_bhh, *wout_, *bout;
    float* out;
};

__global__ __launch_bounds__(NTHR) void mega(MArgs a)
{
    extern __shared__ float sm[];
    const int tid  = threadIdx.x;
    const int half = tid >> 8;
    const int htid = tid & 255;
    float* smh = sm + half * 12800;
    const int BIGJ = 1 << 30;
    unsigned bt = 0;

    // S1: pre1 partials (M=512,K=80,KC=32,jt=4,ks=3)
    gemm_stage<32>(XDirect{a.dec, 80}, a.pw1, BIGJ, a.pw1, 80, BIGJ, 0,
                   512, 80, 4, 3, g_P + OFF_P1, 512, smh, half, htid);
    bt += NBLK; gbar(bt);

    // S2: pre2 partials (M=256,K=512,KC=64,jt=2,ks=8); X = relu(pre1-reduce)
    gemm_stage<64>(XPre1Red{g_P + OFF_P1, a.pb1}, a.pw2, BIGJ, a.pw2, 512, BIGJ, 0,
                   256, 512, 2, 8, g_P + OFF_P2, 256, smh, half, htid);
    bt += NBLK; gbar(bt);

    // S4: gruA input GEMM (M=1536,K=384,KC=32,jt=12,ks=12), W col jump at 256 (+512)
    gemm_stage<32>(XPre2Red{g_P + OFF_P2, a.pb2, a.sv}, a.ga_ih, BIGJ, a.ga_ih, 896,
                   256, 512, 1536, 384, 12, 12, g_P + OFF_A, 1536, smh, half, htid);
    bt += NBLK; gbar(bt);

    // S6: wdec partials (M=512,K=512,KC=64,jt=4,ks=8); X = gruA-reduce on the fly.
    //     Side: materialize out_att for later stages.
    {
        XGruARed xga{g_P + OFF_A, a.ga_bih, a.ga_bhh};
        for (int idx = blockIdx.x * NTHR + tid; idx < 64 * 128; idx += NBLK * NTHR) {
            int n = idx >> 7, c = (idx & 127) << 2;
            *reinterpret_cast<float4*>(g_oatt + n * 512 + c) = xga.load4(n, c);
        }
        gemm_stage<64>(xga, a.wdec_, BIGJ, a.wdec_, 512, BIGJ, 0,
                       512, 512, 4, 8, g_P + OFF_W, 512, smh, half, htid);
    }
    bt += NBLK; gbar(bt);

    // S8: fused attention (score+exp+weighted-sum), work-stealing per half
    attention_phase(a.encW, a.enc, a.wattn, a.battn, a.bdec, a.len, smh, half, htid);
    bt += NBLK; gbar(bt);

    // S10: fused wsc|g1 GEMM (M=2048,K=1152,KC=64,jt=16,ks=18); X = out_dec on the fly.
    //      Side: write attn_applied section of d_out.
    {
        XOdecRed xod{g_part, g_wpart, g_oatt, a.sv};
        for (int idx = blockIdx.x * NTHR + tid; idx < 64 * 128; idx += NBLK * NTHR) {
            int n = idx >> 7, c = (idx & 127) << 2;
            *reinterpret_cast<float4*>(a.out + 10240 + (size_t)n * 512 + c) = xod.load4(n, c);
        }
        gemm_stage<64>(xod, a.wsc, 512, a.g1_ih, 1152, BIGJ, 0,
                       2048, 1152, 16, 18, g_P + OFF_G, 2048, smh, half, htid);
    }
    bt += NBLK; gbar(bt);

    // S11: residual = sc + gru1 -> res1
    for (int idx = blockIdx.x * NTHR + tid; idx < 64 * 512; idx += NBLK * NTHR) {
        int n = idx >> 9, j = idx & 511;
        float sc = a.bsc[j], gr = a.g1_bih[j], gz = a.g1_bih[512 + j], gn = a.g1_bih[1024 + j];
        for (int s = 0; s < 18; s++) {
            const float* pp = g_P + OFF_G + (size_t)s * 131072 + (size_t)n * 2048;
            sc += pp[j]; gr += pp[512 + j]; gz += pp[1024 + j]; gn += pp[1536 + j];
        }
        g_res1[idx] = sc + gru_out(gr, gz, gn, a.g1_bhh[j], a.g1_bhh[512 + j], a.g1_bhh[1024 + j]);
    }
    bt += NBLK; gbar(bt);

    // S12: g2 GEMM (M=1536,K=512,KC=32,jt=12,ks=16); X = res1
    gemm_stage<32>(XDirect{g_res1, 512}, a.g2_ih, BIGJ, a.g2_ih, 512, BIGJ, 0,
                   1536, 512, 12, 16, g_P + OFF_2, 1536, smh, half, htid);
    bt += NBLK; gbar(bt);

    // S14: wout GEMM (M=160,K=512,KC=32,jt=2,ks=16); X = res1 + gru2-reduce on the fly
    gemm_stage<32>(XGru2Red{g_P + OFF_2, a.g2_bih, a.g2_bhh, g_res1},
                   a.wout_, BIGJ, a.wout_, 512, BIGJ, 0,
                   160, 512, 2, 16, g_P + OFF_O, 160, smh, half, htid);
    bt += NBLK; gbar(bt);

    // S15: wout reduce -> d_out[0:10240]
    for (int idx = blockIdx.x * NTHR + tid; idx < 64 * 160; idx += NBLK * NTHR) {
        int n = idx / 160, j = idx - n * 160;
        float s = a.bout[j];
#pragma unroll
        for (int sp = 0; sp < 16; sp++) s += g_P[OFF_O + sp * 10240 + n * 160 + j];
        a.out[idx] = s;
    }
}

// ---------------- host orchestration ----------------
extern "C" void kernel_launch(void* const* d_in, const int* in_sizes, int n_in,
                              void* d_out, int out_size)
{
    (void)n_in; (void)out_size;
    bool dictord = (in_sizes[4] == 64);
    int b = dictord ? 5 : 4;

    MArgs a;
    a.enc   = (const float*)d_in[0];
    a.encW  = (const float*)d_in[1];
    a.dec   = (const float*)d_in[2];
    a.sv    = (const float*)d_in[3];
    a.len   = (const int*)(dictord ? d_in[4] : d_in[28]);
    a.pw1   = (const float*)d_in[b + 0];
    a.pb1   = (const float*)d_in[b + 1];
    a.pw2   = (const float*)d_in[b + 2];
    a.pb2   = (const float*)d_in[b + 3];
    a.wdec_ = (const float*)d_in[b + 4];
    a.bdec  = (const float*)d_in[b + 5];
    a.ga_ih = (const float*)d_in[b + 6];
    a.ga_bih= (const float*)d_in[b + 8];
    a.ga_bhh= (const float*)d_in[b + 9];
    a.wattn = (const float*)d_in[b + 10];
    a.battn = (const float*)d_in[b + 11];
    a.wsc   = (const float*)d_in[b + 12];
    a.bsc   = (const float*)d_in[b + 13];
    a.g1_ih = (const float*)d_in[b + 14];
    a.g1_bih= (const float*)d_in[b + 16];
    a.g1_bhh= (const float*)d_in[b + 17];
    a.g2_ih = (const float*)d_in[b + 18];
    a.g2_bih= (const float*)d_in[b + 20];
    a.g2_bhh= (const float*)d_in[b + 21];
    a.wout_ = (const float*)d_in[b + 22];
    a.bout  = (const float*)d_in[b + 23];
    a.out   = (float*)d_out;

    static bool attr_set = false;
    if (!attr_set) {
        cudaFuncSetAttribute(mega, cudaFuncAttributeMaxDynamicSharedMemorySize, 102400);
        attr_set = true;
    }

    void* ctr;
    cudaGetSymbolAddress(&ctr, g_ctrs);
    cudaMemsetAsync(ctr, 0, 2 * sizeof(unsigned));

    mega<<<NBLK, NTHR, 102400>>>(a);
}